// round 3
// baseline (speedup 1.0000x reference)
#include <cuda_runtime.h>

#define NA_ 40000
#define NE_ 150000

// ---- shared memory layout (floats) ----
#define XS 12            // xT / hT row stride ([64][XS], cols = tokens)
#define QS 212           // qkv row stride ([8][QS]) : q[0:64] k[64:128] v[128:192]

#define W_WB   0
#define W_WQKV 4096
#define W_WO   16384
#define W_W1   20480
#define W_W2   24576
#define B_BB   28672
#define B_BQKV (B_BB + 64)
#define B_BO   (B_BB + 256)
#define B_G1   (B_BB + 320)
#define B_BE1  (B_BB + 384)
#define B_BF1  (B_BB + 448)
#define B_BF2  (B_BB + 512)
#define B_G2   (B_BB + 576)
#define B_BE2  (B_BB + 640)
#define SCR    29376
#define WARP_FLOATS (768 + 768 + 8*QS)      // xT + hT + qkv = 3232
#define SMEM_FLOATS (SCR + 8*WARP_FLOATS)   // 55232
#define SMEM_BYTES  (SMEM_FLOATS * 4)       // 220928 B  (< 227 KB limit)

// per-edge-type accumulators (scratch: __device__ globals, no allocs)
__device__ __align__(16) float g_accum[2][NA_][256];
__device__ __align__(16) float g_cnt[2][NA_];

__global__ void zero_kernel() {
    float4* a = (float4*)&g_accum[0][0][0];
    const int n4 = 2 * NA_ * 64;  // 5,120,000 float4
    for (int i = blockIdx.x * blockDim.x + threadIdx.x; i < n4;
         i += gridDim.x * blockDim.x)
        a[i] = make_float4(0.f, 0.f, 0.f, 0.f);
    float4* c = (float4*)&g_cnt[0][0];
    const int c4 = 2 * NA_ / 4;
    for (int i = blockIdx.x * blockDim.x + threadIdx.x; i < c4;
         i += gridDim.x * blockDim.x)
        c[i] = make_float4(0.f, 0.f, 0.f, 0.f);
}

// layer-norm over 64 channels; lane holds channels (lane, lane+32)
__device__ __forceinline__ float2 warp_ln(float v0, float v1,
                                          const float* __restrict__ g,
                                          const float* __restrict__ b,
                                          int lane) {
    float sum = v0 + v1;
    float sq  = v0 * v0 + v1 * v1;
#pragma unroll
    for (int off = 16; off; off >>= 1) {
        sum += __shfl_xor_sync(0xffffffffu, sum, off);
        sq  += __shfl_xor_sync(0xffffffffu, sq, off);
    }
    float m   = sum * (1.0f / 64.0f);
    float var = sq * (1.0f / 64.0f) - m * m;
    float rs  = rsqrtf(var + 1e-5f);
    return make_float2((v0 - m) * rs * g[lane] + b[lane],
                       (v1 - m) * rs * g[lane + 32] + b[lane + 32]);
}

__global__ void __launch_bounds__(256, 1) edge_kernel(
    const float* __restrict__ xA, const float* __restrict__ xB,
    const int* __restrict__ e_ba, const int* __restrict__ e_aa,
    const float* __restrict__ Wb, const float* __restrict__ bb,
    const float* __restrict__ Wqkv, const float* __restrict__ bqkv,
    const float* __restrict__ Wo, const float* __restrict__ bo,
    const float* __restrict__ g1, const float* __restrict__ be1,
    const float* __restrict__ W1, const float* __restrict__ bf1,
    const float* __restrict__ W2, const float* __restrict__ bf2,
    const float* __restrict__ g2, const float* __restrict__ be2)
{
    extern __shared__ float sm[];
    const int k   = blockIdx.y;
    const int tid = threadIdx.x;

    // ---- load transposed weights into smem ----
    {
        const float* s1 = Wb + k * 4096;
        const float* s2 = Wo + k * 4096;
        const float* s3 = W1 + k * 4096;
        const float* s4 = W2 + k * 4096;
        for (int i = tid; i < 4096; i += 256) {
            int o = i >> 6, c = i & 63;
            sm[W_WB + c * 64 + o] = s1[i];   // WbT[c][f]  = Wb[f][c]
            sm[W_WO + c * 64 + o] = s2[i];   // WoT[c][f]  = Wo[f][c]
            sm[W_W1 + c * 64 + o] = s3[i];   // W1T[c][f]  = W1[f][c]
            sm[W_W2 + c * 64 + o] = s4[i];   // W2T[f][c]  = W2[c][f]
        }
        const float* sq = Wqkv + k * 12288;
        for (int i = tid; i < 12288; i += 256) {
            int o = i >> 6, c = i & 63;
            sm[W_WQKV + c * 192 + o] = sq[i]; // WqkvT[c][f]
        }
        if (tid < 64) {
            sm[B_BB  + tid] = bb [k * 64 + tid];
            sm[B_BO  + tid] = bo [k * 64 + tid];
            sm[B_G1  + tid] = g1 [k * 64 + tid];
            sm[B_BE1 + tid] = be1[k * 64 + tid];
            sm[B_BF1 + tid] = bf1[k * 64 + tid];
            sm[B_BF2 + tid] = bf2[k * 64 + tid];
            sm[B_G2  + tid] = g2 [k * 64 + tid];
            sm[B_BE2 + tid] = be2[k * 64 + tid];
        }
        if (tid < 192) sm[B_BQKV + tid] = bqkv[k * 192 + tid];
    }
    __syncthreads();

    const float* xdst = xA;
    const float* xsrc = (k == 0) ? xB : xA;
    const int*   Es   = (k == 0) ? e_ba : e_aa;      // src indices
    const int*   Ed   = Es + NE_;                    // dst indices
    float* accum = &g_accum[k][0][0];
    float* cnt   = &g_cnt[k][0];

    const int lane = tid & 31;
    const int wrp  = tid >> 5;
    float* xT = sm + SCR + wrp * WARP_FLOATS;  // [64][XS] transposed x (cols = tokens)
    float* hT = xT + 768;                      // [64][XS] src staging / FF hidden
    float* qk = hT + 768;                      // [8][QS] qkv rows; q slot reused for attn out
    const float* WbT = sm + W_WB;
    const float* WqT = sm + W_WQKV;
    const float* WoT = sm + W_WO;
    const float* W1T = sm + W_W1;
    const float* W2T = sm + W_W2;

    for (int e = blockIdx.x * 8 + wrp; e < NE_; e += gridDim.x * 8) {
        const int si = Es[e], di = Ed[e];
        const float4* dr  = (const float4*)(xdst + (size_t)di * 256);
        const float4* srw = (const float4*)(xsrc + (size_t)si * 256);
        // stage xi -> xT[:, 0..3], x_src -> hT[:, 0..3]
#pragma unroll
        for (int r = 0; r < 2; r++) {
            int j = lane + r * 32;
            float4 dv = dr[j];
            float4 sv = srw[j];
            int t = j >> 4, c0 = (j & 15) << 2;
            xT[(c0 + 0) * XS + t] = dv.x; xT[(c0 + 1) * XS + t] = dv.y;
            xT[(c0 + 2) * XS + t] = dv.z; xT[(c0 + 3) * XS + t] = dv.w;
            hT[(c0 + 0) * XS + t] = sv.x; hT[(c0 + 1) * XS + t] = sv.y;
            hT[(c0 + 2) * XS + t] = sv.z; hT[(c0 + 3) * XS + t] = sv.w;
        }
        __syncwarp();

        // ---- b_proj: xT[:, 4..7] = x_src @ Wb^T + bb ----
        {
            float a0[4], a1[4];
            float b0 = sm[B_BB + lane], b1 = sm[B_BB + 32 + lane];
#pragma unroll
            for (int t = 0; t < 4; t++) { a0[t] = b0; a1[t] = b1; }
#pragma unroll 4
            for (int c = 0; c < 64; c++) {
                float4 xv = *(const float4*)(hT + c * XS);
                float w0 = WbT[c * 64 + lane], w1 = WbT[c * 64 + 32 + lane];
                a0[0] += xv.x * w0; a0[1] += xv.y * w0; a0[2] += xv.z * w0; a0[3] += xv.w * w0;
                a1[0] += xv.x * w1; a1[1] += xv.y * w1; a1[2] += xv.z * w1; a1[3] += xv.w * w1;
            }
            *(float4*)(xT + lane * XS + 4)        = make_float4(a0[0], a0[1], a0[2], a0[3]);
            *(float4*)(xT + (lane + 32) * XS + 4) = make_float4(a1[0], a1[1], a1[2], a1[3]);
        }
        __syncwarp();

        // ---- QKV: q for s<4 only; k,v for all 8 tokens ----
        {
            float aq[2][4], ar[4][8];
#pragma unroll
            for (int j = 0; j < 2; j++) {
                float b = sm[B_BQKV + j * 32 + lane];
#pragma unroll
                for (int s = 0; s < 4; s++) aq[j][s] = b;
            }
#pragma unroll
            for (int j = 0; j < 4; j++) {
                float b = sm[B_BQKV + 64 + j * 32 + lane];
#pragma unroll
                for (int s = 0; s < 8; s++) ar[j][s] = b;
            }
#pragma unroll 2
            for (int c = 0; c < 64; c++) {
                float4 xa = *(const float4*)(xT + c * XS);
                float4 xb = *(const float4*)(xT + c * XS + 4);
                const float* wr = WqT + c * 192 + lane;
#pragma unroll
                for (int j = 0; j < 2; j++) {
                    float w = wr[j * 32];
                    aq[j][0] += xa.x * w; aq[j][1] += xa.y * w;
                    aq[j][2] += xa.z * w; aq[j][3] += xa.w * w;
                }
#pragma unroll
                for (int j = 0; j < 4; j++) {
                    float w = wr[64 + j * 32];
                    ar[j][0] += xa.x * w; ar[j][1] += xa.y * w;
                    ar[j][2] += xa.z * w; ar[j][3] += xa.w * w;
                    ar[j][4] += xb.x * w; ar[j][5] += xb.y * w;
                    ar[j][6] += xb.z * w; ar[j][7] += xb.w * w;
                }
            }
#pragma unroll
            for (int j = 0; j < 2; j++)
#pragma unroll
                for (int s = 0; s < 4; s++) qk[s * QS + j * 32 + lane] = aq[j][s];
#pragma unroll
            for (int j = 0; j < 4; j++)
#pragma unroll
                for (int s = 0; s < 8; s++) qk[s * QS + 64 + j * 32 + lane] = ar[j][s];
        }
        __syncwarp();

        // ---- attention: 16 lanes, lane = h*4 + s (queries s<4 only) ----
        if (lane < 16) {
            const int h2 = lane >> 2, s = lane & 3;
            const float* qr = qk + s * QS + h2 * 16;
            float qv[16];
            *(float4*)(qv)      = *(const float4*)(qr);
            *(float4*)(qv + 4)  = *(const float4*)(qr + 4);
            *(float4*)(qv + 8)  = *(const float4*)(qr + 8);
            *(float4*)(qv + 12) = *(const float4*)(qr + 12);
            float sc[8];
            float mx = -1e30f;
#pragma unroll
            for (int t = 0; t < 8; t++) {
                const float* kr = qk + t * QS + 64 + h2 * 16;
                float kv[16];
                *(float4*)(kv)      = *(const float4*)(kr);
                *(float4*)(kv + 4)  = *(const float4*)(kr + 4);
                *(float4*)(kv + 8)  = *(const float4*)(kr + 8);
                *(float4*)(kv + 12) = *(const float4*)(kr + 12);
                float d = 0.f;
#pragma unroll
                for (int dd = 0; dd < 16; dd++) d += qv[dd] * kv[dd];
                d *= 0.25f;  // 1/sqrt(16)
                sc[t] = d;
                mx = fmaxf(mx, d);
            }
            float sum = 0.f;
#pragma unroll
            for (int t = 0; t < 8; t++) {
                float p = __expf(sc[t] - mx);
                sc[t] = p;
                sum += p;
            }
            float inv = 1.0f / sum;
            float ov[16];
#pragma unroll
            for (int dd = 0; dd < 16; dd++) ov[dd] = 0.f;
#pragma unroll
            for (int t = 0; t < 8; t++) {
                const float* vr = qk + t * QS + 128 + h2 * 16;
                float vv[16];
                *(float4*)(vv)      = *(const float4*)(vr);
                *(float4*)(vv + 4)  = *(const float4*)(vr + 4);
                *(float4*)(vv + 8)  = *(const float4*)(vr + 8);
                *(float4*)(vv + 12) = *(const float4*)(vr + 12);
                float p = sc[t];
#pragma unroll
                for (int dd = 0; dd < 16; dd++) ov[dd] += p * vv[dd];
            }
            float* orow = qk + s * QS + h2 * 16;  // overwrite q slot
#pragma unroll
            for (int dd = 0; dd < 16; dd++) ov[dd] *= inv;
            *(float4*)(orow)      = make_float4(ov[0], ov[1], ov[2], ov[3]);
            *(float4*)(orow + 4)  = make_float4(ov[4], ov[5], ov[6], ov[7]);
            *(float4*)(orow + 8)  = make_float4(ov[8], ov[9], ov[10], ov[11]);
            *(float4*)(orow + 12) = make_float4(ov[12], ov[13], ov[14], ov[15]);
        }
        __syncwarp();

        // ---- Wo proj + residual + LN1 (s<4) -> xT ----
        {
            float a0[4], a1[4];
            float b0 = sm[B_BO + lane], b1 = sm[B_BO + 32 + lane];
#pragma unroll
            for (int s = 0; s < 4; s++) { a0[s] = b0; a1[s] = b1; }
#pragma unroll 4
            for (int c2 = 0; c2 < 64; c2++) {
                float w0 = WoT[c2 * 64 + lane], w1 = WoT[c2 * 64 + 32 + lane];
#pragma unroll
                for (int s = 0; s < 4; s++) {
                    float ov = qk[s * QS + c2];
                    a0[s] += ov * w0;
                    a1[s] += ov * w1;
                }
            }
#pragma unroll
            for (int s = 0; s < 4; s++) {
                float v0 = a0[s] + xT[lane * XS + s];
                float v1 = a1[s] + xT[(lane + 32) * XS + s];
                float2 y = warp_ln(v0, v1, sm + B_G1, sm + B_BE1, lane);
                xT[lane * XS + s]        = y.x;
                xT[(lane + 32) * XS + s] = y.y;
            }
        }
        __syncwarp();

        // ---- FF1 (s<4): relu(x @ W1^T + bf1) -> hT transposed ----
        {
            float a0[4], a1[4];
            float b0 = sm[B_BF1 + lane], b1 = sm[B_BF1 + 32 + lane];
#pragma unroll
            for (int s = 0; s < 4; s++) { a0[s] = b0; a1[s] = b1; }
#pragma unroll 4
            for (int c = 0; c < 64; c++) {
                float4 xa = *(const float4*)(xT + c * XS);
                float w0 = W1T[c * 64 + lane], w1 = W1T[c * 64 + 32 + lane];
                a0[0] += xa.x * w0; a0[1] += xa.y * w0; a0[2] += xa.z * w0; a0[3] += xa.w * w0;
                a1[0] += xa.x * w1; a1[1] += xa.y * w1; a1[2] += xa.z * w1; a1[3] += xa.w * w1;
            }
#pragma unroll
            for (int s = 0; s < 4; s++) {
                a0[s] = fmaxf(a0[s], 0.f);
                a1[s] = fmaxf(a1[s], 0.f);
            }
            *(float4*)(hT + lane * XS)        = make_float4(a0[0], a0[1], a0[2], a0[3]);
            *(float4*)(hT + (lane + 32) * XS) = make_float4(a1[0], a1[1], a1[2], a1[3]);
        }
        __syncwarp();

        // ---- FF2 + residual + LN2 (s<4) + atomic scatter ----
        {
            float a0[4], a1[4];
            float b0 = sm[B_BF2 + lane], b1 = sm[B_BF2 + 32 + lane];
#pragma unroll
            for (int s = 0; s < 4; s++) { a0[s] = b0; a1[s] = b1; }
#pragma unroll 4
            for (int f = 0; f < 64; f++) {
                float4 ha = *(const float4*)(hT + f * XS);
                float w0 = W2T[f * 64 + lane], w1 = W2T[f * 64 + 32 + lane];
                a0[0] += ha.x * w0; a0[1] += ha.y * w0; a0[2] += ha.z * w0; a0[3] += ha.w * w0;
                a1[0] += ha.x * w1; a1[1] += ha.y * w1; a1[2] += ha.z * w1; a1[3] += ha.w * w1;
            }
            float* outp = accum + (size_t)di * 256;
#pragma unroll
            for (int s = 0; s < 4; s++) {
                float v0 = a0[s] + xT[lane * XS + s];
                float v1 = a1[s] + xT[(lane + 32) * XS + s];
                float2 y = warp_ln(v0, v1, sm + B_G2, sm + B_BE2, lane);
                atomicAdd(outp + s * 64 + lane, y.x);
                atomicAdd(outp + s * 64 + 32 + lane, y.y);
            }
            if (lane == 0) atomicAdd(cnt + di, 1.0f);
        }
        __syncwarp();  // protect smem before next edge's staging
    }
}

// final head: mean-combine, Wout, token-sum, softmax; one warp per node
__global__ void __launch_bounds__(256) final_kernel(
    const float* __restrict__ Wout, const float* __restrict__ bout,
    float* __restrict__ out)
{
    __shared__ float WoT[2048];     // WoutT[c][o]
    __shared__ float xs[8][64];
    const int tid = threadIdx.x;
    for (int i = tid; i < 2048; i += 256) {
        int o = i >> 6, c = i & 63;
        WoT[c * 32 + o] = Wout[i];
    }
    __syncthreads();
    const int wrp = tid >> 5, lane = tid & 31;
    const int n = blockIdx.x * 8 + wrp;
    if (n >= NA_) return;

    float c0 = g_cnt[0][n], c1 = g_cnt[1][n];
    float i0 = (c0 > 0.f) ? 0.5f / c0 : 0.f;
    float i1 = (c1 > 0.f) ? 0.5f / c1 : 0.f;
    const float* a0p = &g_accum[0][n][0];
    const float* a1p = &g_accum[1][n][0];
    float s0 = 0.f, s1 = 0.f;
#pragma unroll
    for (int t = 0; t < 4; t++) {
        s0 += a0p[t * 64 + lane]      * i0 + a1p[t * 64 + lane]      * i1;
        s1 += a0p[t * 64 + 32 + lane] * i0 + a1p[t * 64 + 32 + lane] * i1;
    }
    xs[wrp][lane]      = s0;
    xs[wrp][lane + 32] = s1;
    __syncwarp();

    float lg = 4.0f * bout[lane];   // sum over T of per-token bias
#pragma unroll
    for (int c = 0; c < 64; c++) lg += xs[wrp][c] * WoT[c * 32 + lane];

    float m = lg;
#pragma unroll
    for (int off = 16; off; off >>= 1) m = fmaxf(m, __shfl_xor_sync(0xffffffffu, m, off));
    float ev = __expf(lg - m);
    float sum = ev;
#pragma unroll
    for (int off = 16; off; off >>= 1) sum += __shfl_xor_sync(0xffffffffu, sum, off);
    out[(size_t)n * 32 + lane] = ev / sum;
}

extern "C" void kernel_launch(void* const* d_in, const int* in_sizes, int n_in,
                              void* d_out, int out_size) {
    const float* xA   = (const float*)d_in[0];
    const float* xB   = (const float*)d_in[1];
    const int*   e_ba = (const int*)d_in[2];
    const int*   e_aa = (const int*)d_in[3];
    const float* Wb   = (const float*)d_in[4];
    const float* bb   = (const float*)d_in[5];
    const float* Wqkv = (const float*)d_in[6];
    const float* bqkv = (const float*)d_in[7];
    const float* Wo   = (const float*)d_in[8];
    const float* bo   = (const float*)d_in[9];
    const float* g1   = (const float*)d_in[10];
    const float* be1  = (const float*)d_in[11];
    const float* W1   = (const float*)d_in[12];
    const float* bf1  = (const float*)d_in[13];
    const float* W2   = (const float*)d_in[14];
    const float* bf2  = (const float*)d_in[15];
    const float* g2   = (const float*)d_in[16];
    const float* be2  = (const float*)d_in[17];
    const float* Wout = (const float*)d_in[18];
    const float* bout = (const float*)d_in[19];

    cudaFuncSetAttribute(edge_kernel,
                         cudaFuncAttributeMaxDynamicSharedMemorySize, SMEM_BYTES);

    zero_kernel<<<1024, 256>>>();
    edge_kernel<<<dim3(148, 2), 256, SMEM_BYTES>>>(
        xA, xB, e_ba, e_aa, Wb, bb, Wqkv, bqkv, Wo, bo,
        g1, be1, W1, bf1, W2, bf2, g2, be2);
    final_kernel<<<(NA_ + 7) / 8, 256>>>(Wout, bout, (float*)d_out);
}

// round 4
// speedup vs baseline: 1.3331x; 1.3331x over previous
#include <cuda_runtime.h>
typedef unsigned long long u64;
#define NA_ 40000
#define NE_ 150000

#define W_WB 0
#define W_WQKV 4096
#define W_WO 16384
#define W_W1 20480
#define W_W2 24576
#define B_BB 28672
#define B_BQKV (B_BB+64)
#define B_BO (B_BB+256)
#define B_G1 (B_BB+320)
#define B_BE1 (B_BB+384)
#define B_BF1 (B_BB+448)
#define B_BF2 (B_BB+512)
#define B_G2 (B_BB+576)
#define B_BE2 (B_BB+640)
#define SCR 29376
// per-edge scratch: xC[64][8]=512 | KC=512 | VC=512 | QC=256
#define XCo 0
#define KCo 512
#define VCo 1024
#define QCo 1536
#define EF 1792
#define WF (2*EF)
#define SMEM_BYTES ((SCR+8*WF)*4)   // 232192 <= 232448

__device__ __align__(16) float g_accum[2][NA_][256];
__device__ __align__(16) float g_cnt[2][NA_];

__global__ void zero_kernel() {
    float4* a = (float4*)&g_accum[0][0][0];
    const int n4 = 2*NA_*64;
    for (int i = blockIdx.x*blockDim.x+threadIdx.x; i < n4; i += gridDim.x*blockDim.x)
        a[i] = make_float4(0.f,0.f,0.f,0.f);
    float4* c = (float4*)&g_cnt[0][0];
    for (int i = blockIdx.x*blockDim.x+threadIdx.x; i < 2*NA_/4; i += gridDim.x*blockDim.x)
        c[i] = make_float4(0.f,0.f,0.f,0.f);
}

__device__ __forceinline__ u64 pk2(float a, float b) {
    u64 r; asm("mov.b64 %0,{%1,%2};" : "=l"(r) : "f"(a), "f"(b)); return r;
}
__device__ __forceinline__ void upk2(u64 v, float& a, float& b) {
    asm("mov.b64 {%0,%1},%2;" : "=f"(a), "=f"(b) : "l"(v));
}
__device__ __forceinline__ void fma2(u64& d, u64 a, u64 b) {
    asm("fma.rn.f32x2 %0,%1,%2,%0;" : "+l"(d) : "l"(a), "l"(b));
}
__device__ __forceinline__ void lnpair(float& v0, float& v1, float ga, float gb,
                                       float ba, float bb2) {
    float sum = v0+v1, sq = v0*v0+v1*v1;
#pragma unroll
    for (int o = 16; o; o >>= 1) {
        sum += __shfl_xor_sync(~0u, sum, o);
        sq  += __shfl_xor_sync(~0u, sq, o);
    }
    float m = sum*(1.f/64.f);
    float rs = rsqrtf(sq*(1.f/64.f)-m*m+1e-5f);
    v0 = (v0-m)*rs*ga+ba; v1 = (v1-m)*rs*gb+bb2;
}
__device__ __forceinline__ void red2(float* p, float a, float b) {
    asm volatile("red.global.add.v2.f32 [%0],{%1,%2};" :: "l"(p), "f"(a), "f"(b) : "memory");
}

__global__ void __launch_bounds__(256,1) edge_kernel(
    const float* __restrict__ xA, const float* __restrict__ xB,
    const int* __restrict__ e_ba, const int* __restrict__ e_aa,
    const float* __restrict__ Wb, const float* __restrict__ bb,
    const float* __restrict__ Wqkv, const float* __restrict__ bqkv,
    const float* __restrict__ Wo, const float* __restrict__ bo,
    const float* __restrict__ g1, const float* __restrict__ be1,
    const float* __restrict__ W1, const float* __restrict__ bf1,
    const float* __restrict__ W2, const float* __restrict__ bf2,
    const float* __restrict__ g2, const float* __restrict__ be2)
{
    extern __shared__ float sm[];
    const int k = blockIdx.y, tid = threadIdx.x;
    {
        const float* s1 = Wb + k*4096;  const float* s2 = Wo + k*4096;
        const float* s3 = W1 + k*4096;  const float* s4 = W2 + k*4096;
        for (int i = tid; i < 4096; i += 256) {
            int o = i>>6, c = i&63;
            sm[W_WB + c*64 + o] = s1[i];
            sm[W_WO + c*64 + o] = s2[i];
            sm[W_W1 + c*64 + o] = s3[i];
            sm[W_W2 + c*64 + o] = s4[i];
        }
        const float* sq = Wqkv + k*12288;
        for (int i = tid; i < 12288; i += 256) {
            int o = i>>6, c = i&63;
            sm[W_WQKV + c*192 + o] = sq[i];
        }
        if (tid < 64) {
            sm[B_BB+tid]=bb[k*64+tid];   sm[B_BO+tid]=bo[k*64+tid];
            sm[B_G1+tid]=g1[k*64+tid];   sm[B_BE1+tid]=be1[k*64+tid];
            sm[B_BF1+tid]=bf1[k*64+tid]; sm[B_BF2+tid]=bf2[k*64+tid];
            sm[B_G2+tid]=g2[k*64+tid];   sm[B_BE2+tid]=be2[k*64+tid];
        }
        if (tid < 192) sm[B_BQKV+tid] = bqkv[k*192+tid];
    }
    __syncthreads();

    const float* xdst = xA;
    const float* xsrc = (k==0) ? xB : xA;
    const int* Es = (k==0) ? e_ba : e_aa;
    const int* Ed = Es + NE_;
    float* accum = &g_accum[k][0][0];
    float* cnt = &g_cnt[k][0];

    const int lane = tid & 31, wrp = tid >> 5;
    const int ch0 = 2*lane;
    float* scr = sm + SCR + wrp*WF;
    const float* WbT = sm+W_WB;  const float* WqT = sm+W_WQKV;
    const float* WoT = sm+W_WO;  const float* W1T = sm+W_W1;
    const float* W2T = sm+W_W2;

    for (int p = blockIdx.x*8 + wrp; p < NE_/2; p += 1184) {
        const int e0 = 2*p, e1 = 2*p+1;
        const int si0 = Es[e0], si1 = Es[e1], di0 = Ed[e0], di1 = Ed[e1];
        float xr[2][2][4], xln[2][2][4];

        // ---- staging: xdst -> xC[c][0..3] + regs, xsrc -> VC[c][0..3] ----
#pragma unroll
        for (int ee = 0; ee < 2; ee++) {
            const float* xd = xdst + (size_t)(ee?di1:di0)*256;
            const float* xp = xsrc + (size_t)(ee?si1:si0)*256;
            float* xc = scr + ee*EF + XCo;
            float* vc = scr + ee*EF + VCo;
            float2 dv[4], sv[4];
#pragma unroll
            for (int s = 0; s < 4; s++) {
                dv[s] = *(const float2*)(xd + s*64 + ch0);
                sv[s] = *(const float2*)(xp + s*64 + ch0);
            }
#pragma unroll
            for (int s = 0; s < 4; s++) { xr[ee][0][s]=dv[s].x; xr[ee][1][s]=dv[s].y; }
            *(float4*)(xc + ch0*8)     = make_float4(dv[0].x,dv[1].x,dv[2].x,dv[3].x);
            *(float4*)(xc + ch0*8 + 8) = make_float4(dv[0].y,dv[1].y,dv[2].y,dv[3].y);
            *(float4*)(vc + ch0*4)     = make_float4(sv[0].x,sv[1].x,sv[2].x,sv[3].x);
            *(float4*)(vc + ch0*4 + 4) = make_float4(sv[0].y,sv[1].y,sv[2].y,sv[3].y);
        }
        __syncwarp();

        // ---- b_proj -> xC tokens 4..7 ----
        {
            float b0f,b1f; upk2(*(const u64*)(sm+B_BB+ch0), b0f,b1f);
            u64 acc[2][2][2];
#pragma unroll
            for (int ee=0; ee<2; ee++) {
                acc[ee][0][0]=acc[ee][0][1]=pk2(b0f,b0f);
                acc[ee][1][0]=acc[ee][1][1]=pk2(b1f,b1f);
            }
            const float* v0p = scr+VCo; const float* v1p = scr+EF+VCo;
#pragma unroll 4
            for (int c = 0; c < 64; c++) {
                float w0,w1; upk2(*(const u64*)(WbT+c*64+ch0), w0,w1);
                u64 w00=pk2(w0,w0), w11=pk2(w1,w1);
                ulonglong2 x0 = *(const ulonglong2*)(v0p + c*4);
                ulonglong2 x1 = *(const ulonglong2*)(v1p + c*4);
                fma2(acc[0][0][0],x0.x,w00); fma2(acc[0][0][1],x0.y,w00);
                fma2(acc[0][1][0],x0.x,w11); fma2(acc[0][1][1],x0.y,w11);
                fma2(acc[1][0][0],x1.x,w00); fma2(acc[1][0][1],x1.y,w00);
                fma2(acc[1][1][0],x1.x,w11); fma2(acc[1][1][1],x1.y,w11);
            }
#pragma unroll
            for (int ee=0; ee<2; ee++) {
                float* xc = scr + ee*EF + XCo;
                *(u64*)(xc+ch0*8+4)  = acc[ee][0][0]; *(u64*)(xc+ch0*8+6)  = acc[ee][0][1];
                *(u64*)(xc+ch0*8+12) = acc[ee][1][0]; *(u64*)(xc+ch0*8+14) = acc[ee][1][1];
            }
        }
        __syncwarp();

        // ---- QKV ----
        {
            float bqa,bqb,bka,bkb,bva,bvb;
            upk2(*(const u64*)(sm+B_BQKV+ch0), bqa,bqb);
            upk2(*(const u64*)(sm+B_BQKV+64+ch0), bka,bkb);
            upk2(*(const u64*)(sm+B_BQKV+128+ch0), bva,bvb);
            u64 aq[2][2][2], ak[2][2][4], av[2][2][4];
#pragma unroll
            for (int ee=0; ee<2; ee++) {
                aq[ee][0][0]=aq[ee][0][1]=pk2(bqa,bqa);
                aq[ee][1][0]=aq[ee][1][1]=pk2(bqb,bqb);
#pragma unroll
                for (int q=0;q<4;q++) {
                    ak[ee][0][q]=pk2(bka,bka); ak[ee][1][q]=pk2(bkb,bkb);
                    av[ee][0][q]=pk2(bva,bva); av[ee][1][q]=pk2(bvb,bvb);
                }
            }
#pragma unroll 2
            for (int c = 0; c < 64; c++) {
                const float* wr = WqT + c*192 + ch0;
                float q0,q1,k0,k1,v0,v1;
                upk2(*(const u64*)(wr), q0,q1);
                upk2(*(const u64*)(wr+64), k0,k1);
                upk2(*(const u64*)(wr+128), v0,v1);
                u64 wq0=pk2(q0,q0),wq1=pk2(q1,q1),wk0=pk2(k0,k0),
                    wk1=pk2(k1,k1),wv0=pk2(v0,v0),wv1=pk2(v1,v1);
#pragma unroll
                for (int ee=0; ee<2; ee++) {
                    const float* xc = scr + ee*EF + XCo + c*8;
                    ulonglong2 xlo = *(const ulonglong2*)(xc);
                    ulonglong2 xhi = *(const ulonglong2*)(xc+4);
                    fma2(aq[ee][0][0],xlo.x,wq0); fma2(aq[ee][0][1],xlo.y,wq0);
                    fma2(aq[ee][1][0],xlo.x,wq1); fma2(aq[ee][1][1],xlo.y,wq1);
                    fma2(ak[ee][0][0],xlo.x,wk0); fma2(ak[ee][0][1],xlo.y,wk0);
                    fma2(ak[ee][0][2],xhi.x,wk0); fma2(ak[ee][0][3],xhi.y,wk0);
                    fma2(ak[ee][1][0],xlo.x,wk1); fma2(ak[ee][1][1],xlo.y,wk1);
                    fma2(ak[ee][1][2],xhi.x,wk1); fma2(ak[ee][1][3],xhi.y,wk1);
                    fma2(av[ee][0][0],xlo.x,wv0); fma2(av[ee][0][1],xlo.y,wv0);
                    fma2(av[ee][0][2],xhi.x,wv0); fma2(av[ee][0][3],xhi.y,wv0);
                    fma2(av[ee][1][0],xlo.x,wv1); fma2(av[ee][1][1],xlo.y,wv1);
                    fma2(av[ee][1][2],xhi.x,wv1); fma2(av[ee][1][3],xhi.y,wv1);
                }
            }
#pragma unroll
            for (int ee=0; ee<2; ee++) {
                float* qc = scr + ee*EF + QCo;
                float* kc = scr + ee*EF + KCo;
                float* vc = scr + ee*EF + VCo;
#pragma unroll
                for (int j=0; j<2; j++) {
                    int ch = ch0 + j;
                    float a,b;
                    upk2(aq[ee][j][0],a,b); qc[ch]=a;     qc[64+ch]=b;
                    upk2(aq[ee][j][1],a,b); qc[128+ch]=a; qc[192+ch]=b;
#pragma unroll
                    for (int q=0;q<4;q++) {
                        upk2(ak[ee][j][q],a,b); kc[(2*q)*64+ch]=a; kc[(2*q+1)*64+ch]=b;
                        upk2(av[ee][j][q],a,b); vc[(2*q)*64+ch]=a; vc[(2*q+1)*64+ch]=b;
                    }
                }
            }
        }
        __syncwarp();

        // ---- attention: lane = ee*16 + h*4 + s ----
        {
            const int ee = lane>>4, l2 = lane&15, h2 = l2>>2, s = l2&3;
            const float* base = scr + ee*EF;
            const float* qr = base + QCo + s*64 + h2*16;
            float qv[16];
            *(float4*)(qv)    = *(const float4*)(qr);
            *(float4*)(qv+4)  = *(const float4*)(qr+4);
            *(float4*)(qv+8)  = *(const float4*)(qr+8);
            *(float4*)(qv+12) = *(const float4*)(qr+12);
            float sc[8], mx = -1e30f;
#pragma unroll
            for (int t = 0; t < 8; t++) {
                const float* kr = base + KCo + t*64 + h2*16;
                float kv[16];
                *(float4*)(kv)    = *(const float4*)(kr);
                *(float4*)(kv+4)  = *(const float4*)(kr+4);
                *(float4*)(kv+8)  = *(const float4*)(kr+8);
                *(float4*)(kv+12) = *(const float4*)(kr+12);
                float d = 0.f;
#pragma unroll
                for (int dd = 0; dd < 16; dd++) d += qv[dd]*kv[dd];
                d *= 0.25f;
                sc[t] = d; mx = fmaxf(mx, d);
            }
            float sum = 0.f;
#pragma unroll
            for (int t = 0; t < 8; t++) { sc[t] = __expf(sc[t]-mx); sum += sc[t]; }
            float inv = 1.0f/sum;
            float ov[16];
#pragma unroll
            for (int dd = 0; dd < 16; dd++) ov[dd] = 0.f;
#pragma unroll
            for (int t = 0; t < 8; t++) {
                const float* vr = base + VCo + t*64 + h2*16;
                float vv[16];
                *(float4*)(vv)    = *(const float4*)(vr);
                *(float4*)(vv+4)  = *(const float4*)(vr+4);
                *(float4*)(vv+8)  = *(const float4*)(vr+8);
                *(float4*)(vv+12) = *(const float4*)(vr+12);
                float pw = sc[t];
#pragma unroll
                for (int dd = 0; dd < 16; dd++) ov[dd] += pw*vv[dd];
            }
            __syncwarp();   // all q reads done before output overlays QC
            float* od = (float*)(base + QCo);
#pragma unroll
            for (int dd = 0; dd < 16; dd++) od[(h2*16+dd)*4 + s] = ov[dd]*inv;
        }
        __syncwarp();

        // ---- Wo + residual + LN1 -> regs xln + xC tokens 0..3 ----
        {
            float b0f,b1f; upk2(*(const u64*)(sm+B_BO+ch0), b0f,b1f);
            u64 acc[2][2][2];
#pragma unroll
            for (int ee=0; ee<2; ee++) {
                acc[ee][0][0]=acc[ee][0][1]=pk2(b0f,b0f);
                acc[ee][1][0]=acc[ee][1][1]=pk2(b1f,b1f);
            }
            const float* o0p = scr+QCo; const float* o1p = scr+EF+QCo;
#pragma unroll 4
            for (int c = 0; c < 64; c++) {
                float w0,w1; upk2(*(const u64*)(WoT+c*64+ch0), w0,w1);
                u64 w00=pk2(w0,w0), w11=pk2(w1,w1);
                ulonglong2 x0 = *(const ulonglong2*)(o0p + c*4);
                ulonglong2 x1 = *(const ulonglong2*)(o1p + c*4);
                fma2(acc[0][0][0],x0.x,w00); fma2(acc[0][0][1],x0.y,w00);
                fma2(acc[0][1][0],x0.x,w11); fma2(acc[0][1][1],x0.y,w11);
                fma2(acc[1][0][0],x1.x,w00); fma2(acc[1][0][1],x1.y,w00);
                fma2(acc[1][1][0],x1.x,w11); fma2(acc[1][1][1],x1.y,w11);
            }
            float ga,gb,ba,bb2;
            upk2(*(const u64*)(sm+B_G1+ch0), ga,gb);
            upk2(*(const u64*)(sm+B_BE1+ch0), ba,bb2);
#pragma unroll
            for (int ee=0; ee<2; ee++) {
                float a[2][4];
                upk2(acc[ee][0][0],a[0][0],a[0][1]); upk2(acc[ee][0][1],a[0][2],a[0][3]);
                upk2(acc[ee][1][0],a[1][0],a[1][1]); upk2(acc[ee][1][1],a[1][2],a[1][3]);
#pragma unroll
                for (int s = 0; s < 4; s++) {
                    float v0 = a[0][s] + xr[ee][0][s];
                    float v1 = a[1][s] + xr[ee][1][s];
                    lnpair(v0, v1, ga, gb, ba, bb2);
                    xln[ee][0][s] = v0; xln[ee][1][s] = v1;
                }
                float* xc = scr + ee*EF + XCo;
                *(u64*)(xc+ch0*8)    = pk2(xln[ee][0][0],xln[ee][0][1]);
                *(u64*)(xc+ch0*8+2)  = pk2(xln[ee][0][2],xln[ee][0][3]);
                *(u64*)(xc+ch0*8+8)  = pk2(xln[ee][1][0],xln[ee][1][1]);
                *(u64*)(xc+ch0*8+10) = pk2(xln[ee][1][2],xln[ee][1][3]);
            }
        }
        __syncwarp();

        // ---- FF1: relu -> KC (stride 4) ----
        {
            float b0f,b1f; upk2(*(const u64*)(sm+B_BF1+ch0), b0f,b1f);
            u64 acc[2][2][2];
#pragma unroll
            for (int ee=0; ee<2; ee++) {
                acc[ee][0][0]=acc[ee][0][1]=pk2(b0f,b0f);
                acc[ee][1][0]=acc[ee][1][1]=pk2(b1f,b1f);
            }
            const float* x0p = scr+XCo; const float* x1p = scr+EF+XCo;
#pragma unroll 4
            for (int c = 0; c < 64; c++) {
                float w0,w1; upk2(*(const u64*)(W1T+c*64+ch0), w0,w1);
                u64 w00=pk2(w0,w0), w11=pk2(w1,w1);
                ulonglong2 x0 = *(const ulonglong2*)(x0p + c*8);
                ulonglong2 x1 = *(const ulonglong2*)(x1p + c*8);
                fma2(acc[0][0][0],x0.x,w00); fma2(acc[0][0][1],x0.y,w00);
                fma2(acc[0][1][0],x0.x,w11); fma2(acc[0][1][1],x0.y,w11);
                fma2(acc[1][0][0],x1.x,w00); fma2(acc[1][0][1],x1.y,w00);
                fma2(acc[1][1][0],x1.x,w11); fma2(acc[1][1][1],x1.y,w11);
            }
#pragma unroll
            for (int ee=0; ee<2; ee++) {
                float* kc = scr + ee*EF + KCo;
                float a0,a1;
                upk2(acc[ee][0][0],a0,a1); *(u64*)(kc+ch0*4)   = pk2(fmaxf(a0,0.f),fmaxf(a1,0.f));
                upk2(acc[ee][0][1],a0,a1); *(u64*)(kc+ch0*4+2) = pk2(fmaxf(a0,0.f),fmaxf(a1,0.f));
                upk2(acc[ee][1][0],a0,a1); *(u64*)(kc+ch0*4+4) = pk2(fmaxf(a0,0.f),fmaxf(a1,0.f));
                upk2(acc[ee][1][1],a0,a1); *(u64*)(kc+ch0*4+6) = pk2(fmaxf(a0,0.f),fmaxf(a1,0.f));
            }
        }
        __syncwarp();

        // ---- FF2 + residual + LN2 + scatter ----
        {
            float b0f,b1f; upk2(*(const u64*)(sm+B_BF2+ch0), b0f,b1f);
            u64 acc[2][2][2];
#pragma unroll
            for (int ee=0; ee<2; ee++) {
                acc[ee][0][0]=acc[ee][0][1]=pk2(b0f,b0f);
                acc[ee][1][0]=acc[ee][1][1]=pk2(b1f,b1f);
            }
            const float* h0p = scr+KCo; const float* h1p = scr+EF+KCo;
#pragma unroll 4
            for (int f = 0; f < 64; f++) {
                float w0,w1; upk2(*(const u64*)(W2T+f*64+ch0), w0,w1);
                u64 w00=pk2(w0,w0), w11=pk2(w1,w1);
                ulonglong2 x0 = *(const ulonglong2*)(h0p + f*4);
                ulonglong2 x1 = *(const ulonglong2*)(h1p + f*4);
                fma2(acc[0][0][0],x0.x,w00); fma2(acc[0][0][1],x0.y,w00);
                fma2(acc[0][1][0],x0.x,w11); fma2(acc[0][1][1],x0.y,w11);
                fma2(acc[1][0][0],x1.x,w00); fma2(acc[1][0][1],x1.y,w00);
                fma2(acc[1][1][0],x1.x,w11); fma2(acc[1][1][1],x1.y,w11);
            }
            float ga,gb,ba,bb2;
            upk2(*(const u64*)(sm+B_G2+ch0), ga,gb);
            upk2(*(const u64*)(sm+B_BE2+ch0), ba,bb2);
#pragma unroll
            for (int ee=0; ee<2; ee++) {
                float a[2][4];
                upk2(acc[ee][0][0],a[0][0],a[0][1]); upk2(acc[ee][0][1],a[0][2],a[0][3]);
                upk2(acc[ee][1][0],a[1][0],a[1][1]); upk2(acc[ee][1][1],a[1][2],a[1][3]);
                float* outp = accum + (size_t)(ee?di1:di0)*256;
#pragma unroll
                for (int s = 0; s < 4; s++) {
                    float v0 = a[0][s] + xln[ee][0][s];
                    float v1 = a[1][s] + xln[ee][1][s];
                    lnpair(v0, v1, ga, gb, ba, bb2);
                    red2(outp + s*64 + ch0, v0, v1);
                }
            }
            if (lane == 0) { atomicAdd(cnt+di0, 1.0f); atomicAdd(cnt+di1, 1.0f); }
        }
        __syncwarp();
    }
}

__global__ void __launch_bounds__(256) final_kernel(
    const float* __restrict__ Wout, const float* __restrict__ bout,
    float* __restrict__ out)
{
    __shared__ float WoT[2048];
    __shared__ float xs[8][64];
    const int tid = threadIdx.x;
    for (int i = tid; i < 2048; i += 256) {
        int o = i>>6, c = i&63;
        WoT[c*32+o] = Wout[i];
    }
    __syncthreads();
    const int wrp = tid>>5, lane = tid&31;
    const int n = blockIdx.x*8 + wrp;
    if (n >= NA_) return;
    float c0 = g_cnt[0][n], c1 = g_cnt[1][n];
    float i0 = (c0>0.f) ? 0.5f/c0 : 0.f;
    float i1 = (c1>0.f) ? 0.5f/c1 : 0.f;
    const float* a0p = &g_accum[0][n][0];
    const float* a1p = &g_accum[1][n][0];
    float s0 = 0.f, s1 = 0.f;
#pragma unroll
    for (int t = 0; t < 4; t++) {
        s0 += a0p[t*64+lane]*i0 + a1p[t*64+lane]*i1;
        s1 += a0p[t*64+32+lane]*i0 + a1p[t*64+32+lane]*i1;
    }
    xs[wrp][lane] = s0; xs[wrp][lane+32] = s1;
    __syncwarp();
    float lg = 4.0f*bout[lane];
#pragma unroll
    for (int c = 0; c < 64; c++) lg += xs[wrp][c]*WoT[c*32+lane];
    float m = lg;
#pragma unroll
    for (int o = 16; o; o >>= 1) m = fmaxf(m, __shfl_xor_sync(~0u, m, o));
    float ev = __expf(lg - m);
    float sum = ev;
#pragma unroll
    for (int o = 16; o; o >>= 1) sum += __shfl_xor_sync(~0u, sum, o);
    out[(size_t)n*32 + lane] = ev/sum;
}

extern "C" void kernel_launch(void* const* d_in, const int* in_sizes, int n_in,
                              void* d_out, int out_size) {
    const float* xA   = (const float*)d_in[0];
    const float* xB   = (const float*)d_in[1];
    const int*   e_ba = (const int*)d_in[2];
    const int*   e_aa = (const int*)d_in[3];
    const float* Wb   = (const float*)d_in[4];
    const float* bb   = (const float*)d_in[5];
    const float* Wqkv = (const float*)d_in[6];
    const float* bqkv = (const float*)d_in[7];
    const float* Wo   = (const float*)d_in[8];
    const float* bo   = (const float*)d_in[9];
    const float* g1   = (const float*)d_in[10];
    const float* be1  = (const float*)d_in[11];
    const float* W1   = (const float*)d_in[12];
    const float* bf1  = (const float*)d_in[13];
    const float* W2   = (const float*)d_in[14];
    const float* bf2  = (const float*)d_in[15];
    const float* g2   = (const float*)d_in[16];
    const float* be2  = (const float*)d_in[17];
    const float* Wout = (const float*)d_in[18];
    const float* bout = (const float*)d_in[19];

    cudaFuncSetAttribute(edge_kernel,
                         cudaFuncAttributeMaxDynamicSharedMemorySize, SMEM_BYTES);
    zero_kernel<<<1024, 256>>>();
    edge_kernel<<<dim3(148,2), 256, SMEM_BYTES>>>(
        xA, xB, e_ba, e_aa, Wb, bb, Wqkv, bqkv, Wo, bo,
        g1, be1, W1, bf1, W2, bf2, g2, be2);
    final_kernel<<<(NA_+7)/8, 256>>>(Wout, bout, (float*)d_out);
}